// round 15
// baseline (speedup 1.0000x reference)
#include <cuda_runtime.h>

// eTofts DCE-MRI forward model — round 13: PDL overlap.
// prep computes per-row constants {d, b_cp, b_u, c0} into g_cst (coalesced,
// ~2us), then __threadfence + cudaTriggerProgrammaticLaunchCompletion.
// main (= round-4 main, best measured cold kernel of the winning 16-rows/CTA
// shape: 34.8us) is launched with programmatic stream serialization: it starts
// immediately, issues its cp LDG.128s (independent of prep), THEN
// cudaGridDependencySynchronize() before reading g_cst. The prep hides under
// main's launch ramp + first-wave load latency, eliminating the ~5-7us
// serialized-second-launch penalty measured in rounds 4/9.

#define TT    112
#define BMAX  262144

__device__ __forceinline__ float ex2f(float x) {
    float y;
    asm("ex2.approx.ftz.f32 %0, %1;" : "=f"(y) : "f"(x));
    return y;
}
__device__ __forceinline__ float rcpf(float x) {
    float y;
    asm("rcp.approx.ftz.f32 %0, %1;" : "=f"(y) : "f"(x));
    return y;
}

// per-row constants: {decay d, b_cp, b_u, c0}
__device__ float4 g_cst[BMAX];

// ---------------- prep: fully coalesced constant computation ----------------
__global__ __launch_bounds__(256) void etofts_prep(
    const float* __restrict__ param,
    const float* __restrict__ T10)
{
    __shared__ float sp[768];   // 256 rows * 3 params
    __shared__ float st[256];

    const int tid = threadIdx.x;
    const int r0  = blockIdx.x * 256;

    // coalesced float4 staging of param (768 floats) and T10 (256 floats)
    const float4* p4 = (const float4*)(param + (size_t)r0 * 3);
    if (tid < 192) ((float4*)sp)[tid] = __ldg(&p4[tid]);
    const float4* t4 = (const float4*)(T10 + r0);
    if (tid < 64)  ((float4*)st)[tid] = __ldg(&t4[tid]);
    __syncthreads();

    const float p0  = sp[3 * tid + 0];   // stride 3: conflict-free
    const float p1  = sp[3 * tid + 1];
    const float p2  = sp[3 * tid + 2];
    const float t10 = st[tid];

    const float ktrans = fminf(fmaxf(p0 * 0.2f, 1e-5f),   0.2f);
    const float vp     = fminf(fmaxf(p1 * 0.1f, 0.0005f), 0.1f);
    const float ve     = fminf(fmaxf(p2 * 0.6f, 0.04f),   0.6f);

    const float DELTT = 0.075f;                 // 4.5/60
    const float LOG2E = 1.4426950408889634f;
    const float TR    = 0.005f;
    const float c1    = -(TR * 4.5f * LOG2E);

    float4 c;
    c.x = ex2f(-(ktrans * rcpf(ve)) * (DELTT * LOG2E));  // d
    c.y = c1 * vp;                                       // b_cp
    c.z = c1 * ktrans * DELTT;                           // b_u
    c.w = -(TR * LOG2E) * rcpf(t10);                     // c0

    g_cst[r0 + tid] = c;                                 // coalesced STG.128

    // make writes visible, then allow the dependent grid to proceed
    __threadfence();
    cudaTriggerProgrammaticLaunchCompletion();
}

// ---------------- main: round-4 structure + grid-dependency sync ----------------
__global__ __launch_bounds__(256) void etofts_main(
    const float* __restrict__ cp,
    float* __restrict__ out)
{
    const int lane = threadIdx.x & 31;
    const int w    = (blockIdx.x * blockDim.x + threadIdx.x) >> 5;  // warp id
    const int half = lane >> 4;          // 0 or 1: which row of this warp
    const int sl   = lane & 15;          // lane within 16-wide segment
    const bool active = sl < (TT / 8);   // 14 active lanes per segment

    const int row = 2 * w + half;

    // ---- cp loads FIRST: independent of prep, in flight before the sync ----
    const float4* rowp = (const float4*)(cp + (size_t)row * TT);
    float4 va = make_float4(0.f, 0.f, 0.f, 0.f);
    float4 vb = make_float4(0.f, 0.f, 0.f, 0.f);
    if (active) {
        va = __ldg(&rowp[2 * sl]);
        vb = __ldg(&rowp[2 * sl + 1]);
    }

    // wait for prep's g_cst writes
    cudaGridDependencySynchronize();

    // per-row constants (broadcast within each half-warp)
    const float4 cst = g_cst[row];
    const float d    = cst.x;
    const float b_cp = cst.y;
    const float b_u  = cst.z;
    const float c0   = cst.w;

    const float SINA = 0.25881904510252074f;    // sin(15 deg)
    const float COSA = 0.9659258262890683f;     // cos(15 deg)
    const float numA = 20.0f * SINA;

    // powers of d
    const float d2  = d   * d;
    const float d3  = d2  * d;
    const float d4  = d2  * d2;
    const float d8  = d4  * d4;
    const float d16 = d8  * d8;
    const float d32 = d16 * d16;
    const float d64 = d32 * d32;

    // scan weights (zero where shfl_up would clamp to own value)
    const float w1 = (sl >= 1) ? d8  : 0.0f;
    const float w2 = (sl >= 2) ? d16 : 0.0f;
    const float w4 = (sl >= 4) ? d32 : 0.0f;
    const float w8 = (sl >= 8) ? d64 : 0.0f;

    // local inclusive scan of 8 elements
    const float l0 = va.x;
    const float l1 = fmaf(d, l0, va.y);
    const float l2 = fmaf(d, l1, va.z);
    const float l3 = fmaf(d, l2, va.w);
    const float l4 = fmaf(d, l3, vb.x);
    const float l5 = fmaf(d, l4, vb.y);
    const float l6 = fmaf(d, l5, vb.z);
    const float l7 = fmaf(d, l6, vb.w);

    // width-16 segmented warp scan of segment end-states (factor d^8 per hop)
    float Bv = l7;
    float t;
    t = __shfl_up_sync(0xffffffffu, Bv, 1, 16); Bv = fmaf(t, w1, Bv);
    t = __shfl_up_sync(0xffffffffu, Bv, 2, 16); Bv = fmaf(t, w2, Bv);
    t = __shfl_up_sync(0xffffffffu, Bv, 4, 16); Bv = fmaf(t, w4, Bv);
    t = __shfl_up_sync(0xffffffffu, Bv, 8, 16); Bv = fmaf(t, w8, Bv);

    float U0 = __shfl_up_sync(0xffffffffu, Bv, 1, 16);  // state entering segment
    if (sl == 0) U0 = 0.0f;

    // full IIR state per element: first 4 via powers, last 4 via recurrence
    const float u0 = fmaf(U0, d,  l0);
    const float u1 = fmaf(U0, d2, l1);
    const float u2 = fmaf(U0, d3, l2);
    const float u3 = fmaf(U0, d4, l3);
    const float u4 = fmaf(d, u3, vb.x);
    const float u5 = fmaf(d, u4, vb.y);
    const float u6 = fmaf(d, u5, vb.z);
    const float u7 = fmaf(d, u6, vb.w);

    // signal equation
    float4 ra, rb;
    {
        float E, num, den;
        E = ex2f(fmaf(b_cp, va.x, fmaf(b_u, u0, c0)));
        num = fmaf(E, -numA, numA); den = fmaf(E, -COSA, 1.0f); ra.x = num * rcpf(den);
        E = ex2f(fmaf(b_cp, va.y, fmaf(b_u, u1, c0)));
        num = fmaf(E, -numA, numA); den = fmaf(E, -COSA, 1.0f); ra.y = num * rcpf(den);
        E = ex2f(fmaf(b_cp, va.z, fmaf(b_u, u2, c0)));
        num = fmaf(E, -numA, numA); den = fmaf(E, -COSA, 1.0f); ra.z = num * rcpf(den);
        E = ex2f(fmaf(b_cp, va.w, fmaf(b_u, u3, c0)));
        num = fmaf(E, -numA, numA); den = fmaf(E, -COSA, 1.0f); ra.w = num * rcpf(den);
        E = ex2f(fmaf(b_cp, vb.x, fmaf(b_u, u4, c0)));
        num = fmaf(E, -numA, numA); den = fmaf(E, -COSA, 1.0f); rb.x = num * rcpf(den);
        E = ex2f(fmaf(b_cp, vb.y, fmaf(b_u, u5, c0)));
        num = fmaf(E, -numA, numA); den = fmaf(E, -COSA, 1.0f); rb.y = num * rcpf(den);
        E = ex2f(fmaf(b_cp, vb.z, fmaf(b_u, u6, c0)));
        num = fmaf(E, -numA, numA); den = fmaf(E, -COSA, 1.0f); rb.z = num * rcpf(den);
        E = ex2f(fmaf(b_cp, vb.w, fmaf(b_u, u7, c0)));
        num = fmaf(E, -numA, numA); den = fmaf(E, -COSA, 1.0f); rb.w = num * rcpf(den);
    }

    if (active) {
        float4* outp = (float4*)(out + (size_t)row * TT);
        outp[2 * sl]     = ra;
        outp[2 * sl + 1] = rb;
    }
}

extern "C" void kernel_launch(void* const* d_in, const int* in_sizes, int n_in,
                              void* d_out, int out_size)
{
    const float* param = (const float*)d_in[0];
    const float* T10   = (const float*)d_in[1];
    const float* cp    = (const float*)d_in[2];
    float*       out   = (float*)d_out;

    const int B = in_sizes[1];          // T10 has B elements

    // primary: constant prep
    etofts_prep<<<B / 256, 256>>>(param, T10);

    // secondary: main, with programmatic dependent launch (overlaps prep)
    cudaLaunchConfig_t cfg = {};
    cfg.gridDim  = dim3(B / 16, 1, 1);   // 2 rows/warp, 8 warps/CTA
    cfg.blockDim = dim3(256, 1, 1);
    cfg.dynamicSmemBytes = 0;
    cfg.stream = 0;                      // legacy stream (captured by harness)
    cudaLaunchAttribute attrs[1];
    attrs[0].id = cudaLaunchAttributeProgrammaticStreamSerialization;
    attrs[0].val.programmaticStreamSerializationAllowed = 1;
    cfg.attrs = attrs;
    cfg.numAttrs = 1;
    cudaLaunchKernelEx(&cfg, etofts_main, cp, (float*)d_out);
}